// round 2
// baseline (speedup 1.0000x reference)
#include <cuda_runtime.h>
#include <math.h>
#include <stdint.h>

#define Bb   64
#define Tt   2048
#define LDIM 16
#define HDIM 64
#define Kk   8

#define LOG2E  1.4426950408889634f
#define LN2F   0.6931471805599453f
#define LOG2PI 1.8378770664093453f

#define GSZ  (Bb*Tt*Kk)            // gamma elements
#define PSZ  (Bb*(Tt-1)*Kk*Kk)     // paired elements

// ---------------- scratch (__device__ globals: graph/alloc-rule safe) ----------------
__device__ float g_le [Bb*Tt*Kk];   // emissions log-prob
__device__ float g_A  [Bb*Tt*Kk];   // rescaled forward  (A-tilde)
__device__ float g_Bt [Bb*Tt*Kk];   // rescaled backward (nb)
__device__ float g_cf [Bb*Tt];      // forward per-step rescale offsets g_t
__device__ float g_cb [Bb*Tt];      // backward per-step rescale offsets c_t
__device__ float g_L  [Bb*Tt];      // L_t = lse_k(A-tilde_t)
__device__ float g_lz [Bb*Tt];      // log_Z
__device__ float g_S  [Bb*Tt];      // backward scalar correction S_t
__device__ float g_logpi[Kk];
__device__ float g_Qlog [Kk*Kk];
__device__ float g_Linv0[Kk*LDIM*LDIM];
__device__ float g_LinvT[Kk*LDIM*LDIM];
__device__ float g_ld0[Kk];
__device__ float g_ldT[Kk];

// ---------------- prep: cholesky terms + log-softmax of pi, Q ----------------
__global__ void snlds_prep(const float* __restrict__ pi,
                           const float* __restrict__ Q,
                           const float* __restrict__ init_cov,
                           const float* __restrict__ covs)
{
    __shared__ float S[16][256];   // 16 matrices (8 init + 8 trans), 16x16
    int tid = threadIdx.x;         // 256 threads

    // Sigma = C C^T + 1e-6 I
    for (int e = tid; e < 4096; e += 256) {
        int m  = e >> 8;
        int ij = e & 255;
        int i  = ij >> 4, j = ij & 15;
        const float* C = (m < 8) ? (init_cov + m*256) : (covs + (m-8)*256);
        float s = (i == j) ? 1e-6f : 0.0f;
        #pragma unroll
        for (int d = 0; d < 16; d++) s = fmaf(C[i*16+d], C[j*16+d], s);
        S[m][ij] = s;
    }
    __syncthreads();

    // left-looking cholesky in place: thread = (matrix m, row r)
    int m = tid >> 4, r = tid & 15;
    for (int kk = 0; kk < 16; kk++) {
        if (r == kk) {
            float s = S[m][kk*16+kk];
            for (int e2 = 0; e2 < kk; e2++) { float v = S[m][kk*16+e2]; s -= v*v; }
            S[m][kk*16+kk] = sqrtf(s);
        }
        __syncthreads();
        if (r > kk) {
            float s = S[m][r*16+kk];
            for (int e2 = 0; e2 < kk; e2++) s -= S[m][r*16+e2]*S[m][kk*16+e2];
            S[m][r*16+kk] = s / S[m][kk*16+kk];
        }
        __syncthreads();
    }

    // logdet_half
    if (r == 0) {
        float s = 0.f;
        for (int d = 0; d < 16; d++) s += logf(S[m][d*16+d]);
        if (m < 8) g_ld0[m] = s; else g_ldT[m-8] = s;
    }

    // Linv = L^{-1} by forward substitution: thread = (m, column c)
    {
        int c = r;
        float x[16];
        #pragma unroll
        for (int i2 = 0; i2 < 16; i2++) x[i2] = 0.f;
        for (int i2 = c; i2 < 16; i2++) {
            float s = (i2 == c) ? 1.0f : 0.0f;
            for (int e2 = c; e2 < i2; e2++) s -= S[m][i2*16+e2]*x[e2];
            x[i2] = s / S[m][i2*16+i2];
        }
        float* dst = (m < 8) ? (g_Linv0 + m*256) : (g_LinvT + (m-8)*256);
        for (int i2 = 0; i2 < 16; i2++) dst[i2*16 + c] = x[i2];
    }

    // log-softmax of Q rows
    if (tid < 8) {
        float mx = -1e30f;
        for (int j = 0; j < 8; j++) mx = fmaxf(mx, Q[tid*8+j]);
        float se = 0.f;
        for (int j = 0; j < 8; j++) se += expf(Q[tid*8+j]-mx);
        float l = mx + logf(se);
        for (int j = 0; j < 8; j++) g_Qlog[tid*8+j] = Q[tid*8+j] - l;
    }
    // log-softmax of pi
    if (tid == 8) {
        float mx = -1e30f;
        for (int j = 0; j < 8; j++) mx = fmaxf(mx, pi[j]);
        float se = 0.f;
        for (int j = 0; j < 8; j++) se += expf(pi[j]-mx);
        float l = mx + logf(se);
        for (int j = 0; j < 8; j++) g_logpi[j] = pi[j] - l;
    }
}

// ---------------- emissions ----------------
__global__ void __launch_bounds__(128) snlds_emis(const float* __restrict__ z,
                                                  const float* __restrict__ W1,
                                                  const float* __restrict__ b1,
                                                  const float* __restrict__ W2,
                                                  const float* __restrict__ b2,
                                                  const float* __restrict__ init_mean)
{
    int k  = blockIdx.y;
    int tx = threadIdx.x;
    __shared__ float sW1[HDIM*LDIM];     // [j][d]
    __shared__ float sW2t[HDIM*LDIM];    // transposed: [j][d] = W2[k][d][j]
    __shared__ float sb1[HDIM], sb2[LDIM];
    __shared__ float sLv[LDIM*LDIM], sLv0[LDIM*LDIM], sMean[LDIM];
    __shared__ float sld[2];

    for (int i = tx; i < HDIM*LDIM; i += 128) {
        sW1[i] = W1[k*HDIM*LDIM + i];
        int j = i >> 4, d = i & 15;
        sW2t[i] = W2[k*LDIM*HDIM + d*HDIM + j];
    }
    for (int i = tx; i < 256; i += 128) { sLv[i] = g_LinvT[k*256+i]; sLv0[i] = g_Linv0[k*256+i]; }
    if (tx < HDIM) sb1[tx] = b1[k*HDIM+tx];
    if (tx < LDIM) { sb2[tx] = b2[k*LDIM+tx]; sMean[tx] = init_mean[k*LDIM+tx]; }
    if (tx == 0) { sld[0] = g_ld0[k]; sld[1] = g_ldT[k]; }
    __syncthreads();

    int idx = blockIdx.x*128 + tx;      // over B*T
    int t   = idx & (Tt-1);

    const float4* zc4 = (const float4*)(z + (size_t)idx*LDIM);
    float zc[16];
    {
        float4 a = zc4[0], b = zc4[1], c = zc4[2], d = zc4[3];
        zc[0]=a.x; zc[1]=a.y; zc[2]=a.z; zc[3]=a.w;
        zc[4]=b.x; zc[5]=b.y; zc[6]=b.z; zc[7]=b.w;
        zc[8]=c.x; zc[9]=c.y; zc[10]=c.z; zc[11]=c.w;
        zc[12]=d.x; zc[13]=d.y; zc[14]=d.z; zc[15]=d.w;
    }

    float diff[16];
    float ldh;
    const float* Lmat;
    if (t == 0) {
        #pragma unroll
        for (int d = 0; d < 16; d++) diff[d] = zc[d] - sMean[d];
        ldh = sld[0]; Lmat = sLv0;
    } else {
        const float4* zp4 = zc4 - 4;
        float zp[16];
        {
            float4 a = zp4[0], b = zp4[1], c = zp4[2], d = zp4[3];
            zp[0]=a.x; zp[1]=a.y; zp[2]=a.z; zp[3]=a.w;
            zp[4]=b.x; zp[5]=b.y; zp[6]=b.z; zp[7]=b.w;
            zp[8]=c.x; zp[9]=c.y; zp[10]=c.z; zp[11]=c.w;
            zp[12]=d.x; zp[13]=d.y; zp[14]=d.z; zp[15]=d.w;
        }
        float mu[16];
        #pragma unroll
        for (int d = 0; d < 16; d++) mu[d] = sb2[d];
        #pragma unroll 4
        for (int j = 0; j < HDIM; j++) {
            float acc = sb1[j];
            #pragma unroll
            for (int d = 0; d < 16; d++) acc = fmaf(sW1[j*16+d], zp[d], acc);
            // softplus(x) = max(x,0) + ln2*log2(1 + exp2(-|x|*log2e))
            float ax = fabsf(acc);
            float ee = exp2f(-ax * LOG2E);
            float hj = fmaxf(acc, 0.f) + LN2F * __log2f(1.0f + ee);
            #pragma unroll
            for (int d = 0; d < 16; d++) mu[d] = fmaf(sW2t[j*16+d], hj, mu[d]);
        }
        #pragma unroll
        for (int d = 0; d < 16; d++) diff[d] = zc[d] - mu[d];
        ldh = sld[1]; Lmat = sLv;
    }

    float maha = 0.f;
    #pragma unroll
    for (int d = 0; d < 16; d++) {
        float y = 0.f;
        #pragma unroll
        for (int e = 0; e < 16; e++) y = fmaf(Lmat[d*16+e], diff[e], y);
        maha = fmaf(y, y, maha);
    }
    g_le[(size_t)idx*Kk + k] = -0.5f*maha - ldh - 0.5f*LDIM*LOG2PI;
}

// ---------------- scans: blockIdx.y=0 forward, =1 backward; one warp per batch ----------------
__global__ void __launch_bounds__(32) snlds_scan()
{
    const unsigned FULL = 0xffffffffu;
    int b    = blockIdx.x;
    int lane = threadIdx.x;
    int kk   = lane & 7;     // this lane's state index
    int jj   = lane >> 3;    // reduction sub-index: handles sources j=jj and j=jj+4
    const float* leb = g_le + (size_t)b*Tt*Kk;

    if (blockIdx.y == 0) {
        // forward: A_t[k] = le_t[k] + lse_j(Qlog[j][k] + A_{t-1}[j]) - g_t
        float q0 = g_Qlog[jj*8 + kk];
        float q1 = g_Qlog[(jj+4)*8 + kk];
        float* Ab  = g_A  + (size_t)b*Tt*Kk;
        float* gb  = g_cf + (size_t)b*Tt;

        float A = g_logpi[kk] + leb[kk];
        float c0 = __shfl_sync(FULL, A, 0);
        A -= c0;
        if (lane < 8)  Ab[kk] = A;
        if (lane == 0) gb[0] = c0;

        for (int t = 1; t < Tt; t++) {
            float lek = leb[t*8 + kk];               // early load, consumed late
            float a0 = __shfl_sync(FULL, A, jj);
            float a1 = __shfl_sync(FULL, A, jj+4);
            float v0 = q0 + a0, v1 = q1 + a1;
            float m = fmaxf(v0, v1);
            m = fmaxf(m, __shfl_xor_sync(FULL, m, 8));
            m = fmaxf(m, __shfl_xor_sync(FULL, m, 16));
            float mL = m * LOG2E;
            float e = exp2f(fmaf(v0, LOG2E, -mL)) + exp2f(fmaf(v1, LOG2E, -mL));
            e += __shfl_xor_sync(FULL, e, 8);
            e += __shfl_xor_sync(FULL, e, 16);
            float cc = __shfl_sync(FULL, m, 0);      // common rescale
            A = lek + (m - cc) + LN2F * __log2f(e);
            if (lane < 8)  Ab[t*8 + kk] = A;
            if (lane == 0) gb[t] = cc;
        }
    } else {
        // backward: nb_t[i] = lse_j(Qlog[i][j] + le_{t+1}[j] + nb_{t+1}[j]) - c_t
        float q0 = g_Qlog[kk*8 + jj];
        float q1 = g_Qlog[kk*8 + jj + 4];
        float* Nb  = g_Bt + (size_t)b*Tt*Kk;
        float* cbb = g_cb + (size_t)b*Tt;

        float Bv = 0.0f;
        if (lane < 8)  Nb[(Tt-1)*8 + kk] = 0.0f;

        for (int t = Tt-2; t >= 0; t--) {
            float len = leb[(t+1)*8 + kk];           // le_{t+1}[own index]
            float u = Bv + len;
            float u0 = __shfl_sync(FULL, u, jj);
            float u1 = __shfl_sync(FULL, u, jj+4);
            float v0 = q0 + u0, v1 = q1 + u1;
            float m = fmaxf(v0, v1);
            m = fmaxf(m, __shfl_xor_sync(FULL, m, 8));
            m = fmaxf(m, __shfl_xor_sync(FULL, m, 16));
            float mL = m * LOG2E;
            float e = exp2f(fmaf(v0, LOG2E, -mL)) + exp2f(fmaf(v1, LOG2E, -mL));
            e += __shfl_xor_sync(FULL, e, 8);
            e += __shfl_xor_sync(FULL, e, 16);
            float cc = __shfl_sync(FULL, m, 0);
            Bv = (m - cc) + LN2F * __log2f(e);
            if (lane < 8)  Nb[t*8 + kk] = Bv;
            if (lane == 0) cbb[t] = cc;
        }
    }
}

// ---------------- per-batch normalization: L_t, lz_t, suffix-scan S_t ----------------
__global__ void __launch_bounds__(256) snlds_norm()
{
    int b   = blockIdx.x;
    int tid = threadIdx.x;
    __shared__ float sL[Tt];
    __shared__ float sZ[Tt];
    __shared__ float sS[256];

    const float* Ab = g_A + (size_t)b*Tt*Kk;

    // L_t = lse_k(A-tilde_t)
    for (int t = tid; t < Tt; t += 256) {
        float x0 = Ab[t*8+0], x1 = Ab[t*8+1], x2 = Ab[t*8+2], x3 = Ab[t*8+3];
        float x4 = Ab[t*8+4], x5 = Ab[t*8+5], x6 = Ab[t*8+6], x7 = Ab[t*8+7];
        float m = fmaxf(fmaxf(fmaxf(x0,x1),fmaxf(x2,x3)), fmaxf(fmaxf(x4,x5),fmaxf(x6,x7)));
        float mL = m * LOG2E;
        float e = exp2f(fmaf(x0,LOG2E,-mL)) + exp2f(fmaf(x1,LOG2E,-mL))
                + exp2f(fmaf(x2,LOG2E,-mL)) + exp2f(fmaf(x3,LOG2E,-mL))
                + exp2f(fmaf(x4,LOG2E,-mL)) + exp2f(fmaf(x5,LOG2E,-mL))
                + exp2f(fmaf(x6,LOG2E,-mL)) + exp2f(fmaf(x7,LOG2E,-mL));
        sL[t] = m + LN2F * __log2f(e);
    }
    __syncthreads();

    // lz_t = L_t - L_{t-1} + g_t (t>=1); lz_0 = L_0 + g_0
    for (int t = tid; t < Tt; t += 256) {
        float lz = (t == 0) ? (sL[0] + g_cf[(size_t)b*Tt])
                            : (sL[t] - sL[t-1] + g_cf[(size_t)b*Tt + t]);
        sZ[t] = lz;
        g_lz[(size_t)b*Tt + t] = lz;
        g_L [(size_t)b*Tt + t] = sL[t];
    }
    __syncthreads();

    // suffix scan: S_t = sum_{t'=t}^{T-2} (c_{t'} - lz_{t'+1}); S_{T-1} = 0
    float dv[8];
    float csum = 0.f;
    #pragma unroll
    for (int r = 0; r < 8; r++) {
        int t = tid*8 + r;
        float d = (t < Tt-1) ? (g_cb[(size_t)b*Tt + t] - sZ[t+1]) : 0.f;
        dv[r] = d; csum += d;
    }
    sS[tid] = csum;
    __syncthreads();
    for (int off = 1; off < 256; off <<= 1) {
        float v = sS[tid] + ((tid + off < 256) ? sS[tid + off] : 0.f);
        __syncthreads();
        sS[tid] = v;
        __syncthreads();
    }
    float acc = sS[tid] - csum;     // sum over chunks > tid
    float Sloc[8];
    #pragma unroll
    for (int r = 7; r >= 0; r--) { acc += dv[r]; Sloc[r] = acc; }
    #pragma unroll
    for (int r = 0; r < 8; r++) {
        int t = tid*8 + r;
        g_S[(size_t)b*Tt + t] = Sloc[r];
    }
}

// ---------------- outputs: gamma, paired, log_Z ----------------
__global__ void __launch_bounds__(256) snlds_out(float* __restrict__ out)
{
    __shared__ float seQ[64];
    int tid = threadIdx.x;
    if (tid < 64) seQ[tid] = exp2f(g_Qlog[tid] * LOG2E);
    __syncthreads();

    int gidx = blockIdx.x*32 + (tid >> 3);  // (b,t) flat index; 32 groups per block
    int i    = tid & 7;
    int t    = gidx & (Tt-1);
    int b    = gidx >> 11;

    float L  = g_L[gidx];
    float S  = g_S[gidx];
    float Ai = g_A[(size_t)gidx*8 + i];
    float nbi= g_Bt[(size_t)gidx*8 + i];
    float lai = Ai - L;

    out[(size_t)gidx*8 + i] = exp2f((lai + nbi + S) * LOG2E);        // gamma
    if (i == 0) out[(size_t)GSZ + PSZ + gidx] = g_lz[gidx];          // log_Z

    // paired (computed uniformly with clamped index to keep shfl convergent)
    int gnext = (t < Tt-1) ? (gidx + 1) : gidx;
    float nb1 = g_Bt[(size_t)gnext*8 + i];
    float le1 = g_le[(size_t)gnext*8 + i];
    float lz1 = g_lz[gnext];
    float S1  = g_S[gnext];
    float eB  = exp2f((nb1 + S1 + le1 - lz1) * LOG2E);
    float eA  = exp2f(lai * LOG2E);

    int baseLane = tid & 24;
    float pb[8];
    #pragma unroll
    for (int j = 0; j < 8; j++) pb[j] = __shfl_sync(0xffffffffu, eB, baseLane + j);

    if (t < Tt-1) {
        size_t pbase = (size_t)GSZ + ((size_t)(b*(Tt-1) + t))*64 + (size_t)i*8;
        float4 q0 = *(const float4*)(seQ + i*8);
        float4 q1 = *(const float4*)(seQ + i*8 + 4);
        float4 p0, p1;
        p0.x = eA * q0.x * pb[0];
        p0.y = eA * q0.y * pb[1];
        p0.z = eA * q0.z * pb[2];
        p0.w = eA * q0.w * pb[3];
        p1.x = eA * q1.x * pb[4];
        p1.y = eA * q1.y * pb[5];
        p1.z = eA * q1.z * pb[6];
        p1.w = eA * q1.w * pb[7];
        *(float4*)(out + pbase)     = p0;
        *(float4*)(out + pbase + 4) = p1;
    }
}

extern "C" void kernel_launch(void* const* d_in, const int* in_sizes, int n_in,
                              void* d_out, int out_size) {
    const float* z         = (const float*)d_in[0];
    const float* pi        = (const float*)d_in[1];
    const float* Q         = (const float*)d_in[2];
    const float* init_mean = (const float*)d_in[3];
    const float* init_cov  = (const float*)d_in[4];
    const float* covs      = (const float*)d_in[5];
    const float* W1        = (const float*)d_in[6];
    const float* b1        = (const float*)d_in[7];
    const float* W2        = (const float*)d_in[8];
    const float* b2        = (const float*)d_in[9];
    float* out = (float*)d_out;

    snlds_prep<<<1, 256>>>(pi, Q, init_cov, covs);
    snlds_emis<<<dim3((Bb*Tt)/128, Kk), 128>>>(z, W1, b1, W2, b2, init_mean);
    snlds_scan<<<dim3(Bb, 2), 32>>>();
    snlds_norm<<<Bb, 256>>>();
    snlds_out<<<(Bb*Tt)/32, 256>>>(out);
}

// round 3
// speedup vs baseline: 2.5659x; 2.5659x over previous
#include <cuda_runtime.h>
#include <math.h>
#include <stdint.h>

#define Bb   64
#define Tt   2048
#define LDIM 16
#define HDIM 64
#define Kk   8
#define LC   32
#define CC   64              // Tt / LC

#define LOG2E  1.4426950408889634f
#define LN2F   0.6931471805599453f
#define LOG2PI 1.8378770664093453f

#define GSZ  (Bb*Tt*Kk)            // gamma elements
#define PSZ  (Bb*(Tt-1)*Kk*Kk)     // paired elements

// ---------------- scratch (__device__ globals: graph/alloc-rule safe) ----------------
__device__ __align__(16) float g_le [Bb*Tt*Kk];   // emissions log-prob
__device__ __align__(16) float g_ele[Bb*Tt*Kk];   // exp(le - m_t)  (linear, <=1)
__device__ float g_m  [Bb*Tt];                    // m_t = max_k le
__device__ __align__(16) float g_A  [Bb*Tt*Kk];   // a-hat (scaled forward)
__device__ __align__(16) float g_Bv [Bb*Tt*Kk];   // b-hat (scaled backward)
__device__ float g_sig[Bb*Tt];                    // sum_k a-hat_t
__device__ int   g_E  [Bb*Tt];                    // forward cumulative pow2 exponent
__device__ int   g_F  [Bb*Tt];                    // backward cumulative pow2 exponent
__device__ __align__(16) float g_M  [Bb*CC*64];   // chunk matrices
__device__ int   g_EM [Bb*CC];                    // chunk matrix exponents
__device__ __align__(16) float g_bndA[Bb*CC*8];   // forward boundary vectors
__device__ int   g_EA [Bb*CC];
__device__ __align__(16) float g_bndW[Bb*CC*8];   // backward boundary vectors
__device__ int   g_FW [Bb*CC];
__device__ float g_eQ [64];
__device__ float g_epi[8];
__device__ float g_Qlog[64];
__device__ float g_logpi[8];
__device__ float g_Linv0[Kk*LDIM*LDIM];
__device__ float g_LinvT[Kk*LDIM*LDIM];
__device__ float g_ld0[Kk];
__device__ float g_ldT[Kk];

// rescale 8-vector by 2^-e where e = exponent of max; returns e. (lossless)
__device__ __forceinline__ int rescale8(float* v) {
    float mx = v[0];
    #pragma unroll
    for (int k = 1; k < 8; k++) mx = fmaxf(mx, v[k]);
    int ib = __float_as_int(mx);
    int ee = (ib >> 23) - 127;
    float sc = __int_as_float((254 - (ib >> 23)) << 23);
    #pragma unroll
    for (int k = 0; k < 8; k++) v[k] *= sc;
    return ee;
}

__device__ __forceinline__ void load8(float* dst, const float* src) {
    float4 a = *(const float4*)src;
    float4 b = *(const float4*)(src + 4);
    dst[0]=a.x; dst[1]=a.y; dst[2]=a.z; dst[3]=a.w;
    dst[4]=b.x; dst[5]=b.y; dst[6]=b.z; dst[7]=b.w;
}
__device__ __forceinline__ void store8(float* dst, const float* v) {
    *(float4*)dst       = make_float4(v[0], v[1], v[2], v[3]);
    *(float4*)(dst + 4) = make_float4(v[4], v[5], v[6], v[7]);
}

// ---------------- prep: cholesky terms + log-softmax + linear tables ----------------
__global__ void snlds_prep(const float* __restrict__ pi,
                           const float* __restrict__ Q,
                           const float* __restrict__ init_cov,
                           const float* __restrict__ covs)
{
    __shared__ float S[16][256];   // 16 matrices (8 init + 8 trans), 16x16
    int tid = threadIdx.x;         // 256 threads

    // Sigma = C C^T + 1e-6 I
    for (int e = tid; e < 4096; e += 256) {
        int m  = e >> 8;
        int ij = e & 255;
        int i  = ij >> 4, j = ij & 15;
        const float* C = (m < 8) ? (init_cov + m*256) : (covs + (m-8)*256);
        float s = (i == j) ? 1e-6f : 0.0f;
        #pragma unroll
        for (int d = 0; d < 16; d++) s = fmaf(C[i*16+d], C[j*16+d], s);
        S[m][ij] = s;
    }
    __syncthreads();

    // left-looking cholesky in place: thread = (matrix m, row r)
    int m = tid >> 4, r = tid & 15;
    for (int kk = 0; kk < 16; kk++) {
        if (r == kk) {
            float s = S[m][kk*16+kk];
            for (int e2 = 0; e2 < kk; e2++) { float v = S[m][kk*16+e2]; s -= v*v; }
            S[m][kk*16+kk] = sqrtf(s);
        }
        __syncthreads();
        if (r > kk) {
            float s = S[m][r*16+kk];
            for (int e2 = 0; e2 < kk; e2++) s -= S[m][r*16+e2]*S[m][kk*16+e2];
            S[m][r*16+kk] = s / S[m][kk*16+kk];
        }
        __syncthreads();
    }

    // logdet_half
    if (r == 0) {
        float s = 0.f;
        for (int d = 0; d < 16; d++) s += logf(S[m][d*16+d]);
        if (m < 8) g_ld0[m] = s; else g_ldT[m-8] = s;
    }

    // Linv = L^{-1} by forward substitution: thread = (m, column c)
    {
        int c = r;
        float x[16];
        #pragma unroll
        for (int i2 = 0; i2 < 16; i2++) x[i2] = 0.f;
        for (int i2 = c; i2 < 16; i2++) {
            float s = (i2 == c) ? 1.0f : 0.0f;
            for (int e2 = c; e2 < i2; e2++) s -= S[m][i2*16+e2]*x[e2];
            x[i2] = s / S[m][i2*16+i2];
        }
        float* dst = (m < 8) ? (g_Linv0 + m*256) : (g_LinvT + (m-8)*256);
        for (int i2 = 0; i2 < 16; i2++) dst[i2*16 + c] = x[i2];
    }

    // log-softmax of Q rows
    if (tid < 8) {
        float mx = -1e30f;
        for (int j = 0; j < 8; j++) mx = fmaxf(mx, Q[tid*8+j]);
        float se = 0.f;
        for (int j = 0; j < 8; j++) se += expf(Q[tid*8+j]-mx);
        float l = mx + logf(se);
        for (int j = 0; j < 8; j++) g_Qlog[tid*8+j] = Q[tid*8+j] - l;
    }
    // log-softmax of pi
    if (tid == 8) {
        float mx = -1e30f;
        for (int j = 0; j < 8; j++) mx = fmaxf(mx, pi[j]);
        float se = 0.f;
        for (int j = 0; j < 8; j++) se += expf(pi[j]-mx);
        float l = mx + logf(se);
        for (int j = 0; j < 8; j++) g_logpi[j] = pi[j] - l;
    }
    __syncthreads();
    if (tid < 64) g_eQ[tid] = exp2f(g_Qlog[tid] * LOG2E);
    if (tid < 8)  g_epi[tid] = exp2f(g_logpi[tid] * LOG2E);
}

// ---------------- emissions ----------------
__global__ void __launch_bounds__(128) snlds_emis(const float* __restrict__ z,
                                                  const float* __restrict__ W1,
                                                  const float* __restrict__ b1,
                                                  const float* __restrict__ W2,
                                                  const float* __restrict__ b2,
                                                  const float* __restrict__ init_mean)
{
    int k  = blockIdx.y;
    int tx = threadIdx.x;
    __shared__ float sW1[HDIM*LDIM];     // [j][d]
    __shared__ float sW2t[HDIM*LDIM];    // transposed: [j][d] = W2[k][d][j]
    __shared__ float sb1[HDIM], sb2[LDIM];
    __shared__ float sLv[LDIM*LDIM], sLv0[LDIM*LDIM], sMean[LDIM];
    __shared__ float sld[2];

    for (int i = tx; i < HDIM*LDIM; i += 128) {
        sW1[i] = W1[k*HDIM*LDIM + i];
        int j = i >> 4, d = i & 15;
        sW2t[i] = W2[k*LDIM*HDIM + d*HDIM + j];
    }
    for (int i = tx; i < 256; i += 128) { sLv[i] = g_LinvT[k*256+i]; sLv0[i] = g_Linv0[k*256+i]; }
    if (tx < HDIM) sb1[tx] = b1[k*HDIM+tx];
    if (tx < LDIM) { sb2[tx] = b2[k*LDIM+tx]; sMean[tx] = init_mean[k*LDIM+tx]; }
    if (tx == 0) { sld[0] = g_ld0[k]; sld[1] = g_ldT[k]; }
    __syncthreads();

    int idx = blockIdx.x*128 + tx;      // over B*T
    int t   = idx & (Tt-1);

    const float4* zc4 = (const float4*)(z + (size_t)idx*LDIM);
    float zc[16];
    {
        float4 a = zc4[0], b = zc4[1], c = zc4[2], d = zc4[3];
        zc[0]=a.x; zc[1]=a.y; zc[2]=a.z; zc[3]=a.w;
        zc[4]=b.x; zc[5]=b.y; zc[6]=b.z; zc[7]=b.w;
        zc[8]=c.x; zc[9]=c.y; zc[10]=c.z; zc[11]=c.w;
        zc[12]=d.x; zc[13]=d.y; zc[14]=d.z; zc[15]=d.w;
    }

    float diff[16];
    float ldh;
    const float* Lmat;
    if (t == 0) {
        #pragma unroll
        for (int d = 0; d < 16; d++) diff[d] = zc[d] - sMean[d];
        ldh = sld[0]; Lmat = sLv0;
    } else {
        const float4* zp4 = zc4 - 4;
        float zp[16];
        {
            float4 a = zp4[0], b = zp4[1], c = zp4[2], d = zp4[3];
            zp[0]=a.x; zp[1]=a.y; zp[2]=a.z; zp[3]=a.w;
            zp[4]=b.x; zp[5]=b.y; zp[6]=b.z; zp[7]=b.w;
            zp[8]=c.x; zp[9]=c.y; zp[10]=c.z; zp[11]=c.w;
            zp[12]=d.x; zp[13]=d.y; zp[14]=d.z; zp[15]=d.w;
        }
        float mu[16];
        #pragma unroll
        for (int d = 0; d < 16; d++) mu[d] = sb2[d];
        #pragma unroll 4
        for (int j = 0; j < HDIM; j++) {
            float acc = sb1[j];
            #pragma unroll
            for (int d = 0; d < 16; d++) acc = fmaf(sW1[j*16+d], zp[d], acc);
            float ax = fabsf(acc);
            float ee = exp2f(-ax * LOG2E);
            float hj = fmaxf(acc, 0.f) + LN2F * __log2f(1.0f + ee);
            #pragma unroll
            for (int d = 0; d < 16; d++) mu[d] = fmaf(sW2t[j*16+d], hj, mu[d]);
        }
        #pragma unroll
        for (int d = 0; d < 16; d++) diff[d] = zc[d] - mu[d];
        ldh = sld[1]; Lmat = sLv;
    }

    float maha = 0.f;
    #pragma unroll
    for (int d = 0; d < 16; d++) {
        float y = 0.f;
        #pragma unroll
        for (int e = 0; e < 16; e++) y = fmaf(Lmat[d*16+e], diff[e], y);
        maha = fmaf(y, y, maha);
    }
    g_le[(size_t)idx*Kk + k] = -0.5f*maha - ldh - 0.5f*LDIM*LOG2PI;
}

// ---------------- conversion: m_t = max_k le, ele = exp(le - m) ----------------
__global__ void __launch_bounds__(256) snlds_conv()
{
    int bt = blockIdx.x*256 + threadIdx.x;
    float v[8];
    load8(v, g_le + (size_t)bt*8);
    float m = v[0];
    #pragma unroll
    for (int k = 1; k < 8; k++) m = fmaxf(m, v[k]);
    g_m[bt] = m;
    float mL = m * LOG2E;
    #pragma unroll
    for (int k = 0; k < 8; k++) v[k] = exp2f(fmaf(v[k], LOG2E, -mL));
    store8(g_ele + (size_t)bt*8, v);
}

// ---------------- phase 1: per-chunk 8x8 matrix products (one row per thread) ----------------
__global__ void __launch_bounds__(256) snlds_p1()
{
    int gt = blockIdx.x*256 + threadIdx.x;   // Bb*CC*8 threads
    int i = gt & 7;
    int chain = gt >> 3;                     // b*CC + c
    int c = chain & (CC-1);
    int b = chain >> 6;

    float q[64];
    #pragma unroll
    for (int e = 0; e < 64; e++) q[e] = g_eQ[e];

    float r[8];
    #pragma unroll
    for (int k = 0; k < 8; k++) r[k] = (k == i) ? 1.0f : 0.0f;
    int E = 0;

    const float* eb = g_ele + ((size_t)b*Tt)*8;
    int t0 = c*LC + ((c == 0) ? 1 : 0);
    int t1 = c*LC + LC;
    for (int t = t0; t < t1; t++) {
        float el[8];
        load8(el, eb + (size_t)t*8);
        float n[8];
        #pragma unroll
        for (int k = 0; k < 8; k++) {
            float s = r[0]*q[0*8+k];
            #pragma unroll
            for (int j = 1; j < 8; j++) s = fmaf(r[j], q[j*8+k], s);
            n[k] = s * el[k];
        }
        E += rescale8(n);
        #pragma unroll
        for (int k = 0; k < 8; k++) r[k] = n[k];
    }

    // common exponent across the 8 rows of this chain (adjacent lanes)
    const unsigned FULL = 0xffffffffu;
    int Emax = E;
    Emax = max(Emax, __shfl_xor_sync(FULL, Emax, 1));
    Emax = max(Emax, __shfl_xor_sync(FULL, Emax, 2));
    Emax = max(Emax, __shfl_xor_sync(FULL, Emax, 4));
    int d = E - Emax; if (d < -126) d = -126;
    float sc = __int_as_float((127 + d) << 23);
    #pragma unroll
    for (int k = 0; k < 8; k++) r[k] *= sc;
    store8(g_M + (size_t)chain*64 + i*8, r);
    if (i == 0) g_EM[chain] = Emax;
}

// ---------------- phase 2: serial chunk-boundary vectors ----------------
__global__ void snlds_p2()
{
    int b = threadIdx.x;                     // 64 threads per block
    if (blockIdx.x == 0) {
        // forward boundaries: bndA[c] = alpha_{c*LC - 1} (c>=1); bndA[0] = alpha_0
        float a[8]; int E = 0;
        const float* eb = g_ele + (size_t)b*Tt*8;
        #pragma unroll
        for (int k = 0; k < 8; k++) a[k] = g_epi[k] * eb[k];
        E = rescale8(a);
        store8(g_bndA + (size_t)(b*CC)*8, a);
        g_EA[b*CC] = E;
        for (int c = 0; c < CC-1; c++) {
            const float* Mp = g_M + (size_t)(b*CC + c)*64;
            float Mm[64];
            #pragma unroll
            for (int x = 0; x < 8; x++) load8(Mm + x*8, Mp + x*8);
            float n[8];
            #pragma unroll
            for (int k = 0; k < 8; k++) {
                float s = a[0]*Mm[0*8+k];
                #pragma unroll
                for (int i = 1; i < 8; i++) s = fmaf(a[i], Mm[i*8+k], s);
                n[k] = s;
            }
            E += rescale8(n) + g_EM[b*CC + c];
            #pragma unroll
            for (int k = 0; k < 8; k++) a[k] = n[k];
            store8(g_bndA + (size_t)(b*CC + c + 1)*8, a);
            g_EA[b*CC + c + 1] = E;
        }
    } else {
        // backward boundaries: bndW[c] = b_{(c+1)*LC - 1}
        float w[8]; int F = 0;
        #pragma unroll
        for (int k = 0; k < 8; k++) w[k] = 1.0f;
        store8(g_bndW + (size_t)(b*CC + CC-1)*8, w);
        g_FW[b*CC + CC-1] = 0;
        for (int c = CC-1; c >= 1; c--) {
            const float* Mp = g_M + (size_t)(b*CC + c)*64;
            float Mm[64];
            #pragma unroll
            for (int x = 0; x < 8; x++) load8(Mm + x*8, Mp + x*8);
            float n[8];
            #pragma unroll
            for (int i = 0; i < 8; i++) {
                float s = Mm[i*8+0]*w[0];
                #pragma unroll
                for (int k = 1; k < 8; k++) s = fmaf(Mm[i*8+k], w[k], s);
                n[i] = s;
            }
            F += rescale8(n) + g_EM[b*CC + c];
            #pragma unroll
            for (int k = 0; k < 8; k++) w[k] = n[k];
            store8(g_bndW + (size_t)(b*CC + c - 1)*8, w);
            g_FW[b*CC + c - 1] = F;
        }
    }
}

// ---------------- phase 3: within-chunk vector recursions (thread per chain) ----------------
__global__ void __launch_bounds__(256) snlds_p3()
{
    int chain = blockIdx.x*256 + threadIdx.x;  // Bb*CC chains
    int c = chain & (CC-1);
    int b = chain >> 6;

    float q[64];
    #pragma unroll
    for (int e = 0; e < 64; e++) q[e] = g_eQ[e];

    const float* eb = g_ele + (size_t)b*Tt*8;

    if (blockIdx.y == 0) {
        // forward
        float a[8];
        load8(a, g_bndA + (size_t)chain*8);
        int E = g_EA[chain];
        float* Ad = g_A + (size_t)b*Tt*8;
        int t0 = c*LC;
        if (c == 0) {
            // entry IS t=0: store it
            store8(Ad, a);
            float sg = a[0]+a[1]+a[2]+a[3]+a[4]+a[5]+a[6]+a[7];
            g_sig[b*Tt] = sg; g_E[b*Tt] = E;
            t0 = 1;
        }
        for (int t = t0; t < c*LC + LC; t++) {
            float el[8];
            load8(el, eb + (size_t)t*8);
            float n[8];
            #pragma unroll
            for (int k = 0; k < 8; k++) {
                float s = a[0]*q[0*8+k];
                #pragma unroll
                for (int j = 1; j < 8; j++) s = fmaf(a[j], q[j*8+k], s);
                n[k] = s * el[k];
            }
            E += rescale8(n);
            #pragma unroll
            for (int k = 0; k < 8; k++) a[k] = n[k];
            store8(Ad + (size_t)t*8, a);
            float sg = a[0]+a[1]+a[2]+a[3]+a[4]+a[5]+a[6]+a[7];
            g_sig[b*Tt + t] = sg; g_E[b*Tt + t] = E;
        }
    } else {
        // backward
        float w[8];
        load8(w, g_bndW + (size_t)chain*8);
        int F = g_FW[chain];
        float* Bd = g_Bv + (size_t)b*Tt*8;
        int thi = c*LC + LC - 1;
        store8(Bd + (size_t)thi*8, w);
        g_F[b*Tt + thi] = F;
        for (int t = thi - 1; t >= c*LC; t--) {
            float el[8];
            load8(el, eb + (size_t)(t+1)*8);
            float s8[8];
            #pragma unroll
            for (int j = 0; j < 8; j++) s8[j] = el[j] * w[j];
            float n[8];
            #pragma unroll
            for (int i = 0; i < 8; i++) {
                float s = q[i*8+0]*s8[0];
                #pragma unroll
                for (int j = 1; j < 8; j++) s = fmaf(q[i*8+j], s8[j], s);
                n[i] = s;
            }
            F += rescale8(n);
            #pragma unroll
            for (int k = 0; k < 8; k++) w[k] = n[k];
            store8(Bd + (size_t)t*8, w);
            g_F[b*Tt + t] = F;
        }
    }
}

// ---------------- outputs: gamma, paired, log_Z ----------------
__global__ void __launch_bounds__(256) snlds_out(float* __restrict__ out)
{
    const unsigned FULL = 0xffffffffu;
    __shared__ float seQ[64];
    int tid = threadIdx.x;
    if (tid < 64) seQ[tid] = g_eQ[tid];
    __syncthreads();

    int gidx = blockIdx.x*32 + (tid >> 3);  // (b,t) flat index
    int i    = tid & 7;
    int t    = gidx & (Tt-1);
    int b    = gidx >> 11;

    float ai = g_A [(size_t)gidx*8 + i];
    float bi = g_Bv[(size_t)gidx*8 + i];
    float pr = ai * bi;
    float G = pr;
    G += __shfl_xor_sync(FULL, G, 1);
    G += __shfl_xor_sync(FULL, G, 2);
    G += __shfl_xor_sync(FULL, G, 4);
    float rG = 1.0f / G;
    out[(size_t)gidx*8 + i] = pr * rG;                  // gamma

    if (i == 0) {                                       // log_Z
        float lz;
        if (t == 0) lz = (log2f(g_sig[gidx]) + (float)g_E[gidx]) * LN2F + g_m[gidx];
        else        lz = (log2f(g_sig[gidx]) - log2f(g_sig[gidx-1])
                          + (float)(g_E[gidx] - g_E[gidx-1])) * LN2F + g_m[gidx];
        out[(size_t)GSZ + PSZ + gidx] = lz;
    }

    // paired (uniform shfl; stores guarded)
    int gn = (t < Tt-1) ? (gidx + 1) : gidx;
    float bj = g_Bv [(size_t)gn*8 + i];
    float ej = g_ele[(size_t)gn*8 + i];
    float cj = bj * ej;
    int dF = g_F[gidx] - g_F[gn];
    float pnorm = ldexpf(rG, -dF);

    int baseLane = tid & 24;
    float cb[8];
    #pragma unroll
    for (int j = 0; j < 8; j++) cb[j] = __shfl_sync(FULL, cj, baseLane + j);

    if (t < Tt-1) {
        float eA = ai * pnorm;
        size_t pbase = (size_t)GSZ + ((size_t)(b*(Tt-1) + t))*64 + (size_t)i*8;
        float4 p0, p1;
        p0.x = eA * seQ[i*8+0] * cb[0];
        p0.y = eA * seQ[i*8+1] * cb[1];
        p0.z = eA * seQ[i*8+2] * cb[2];
        p0.w = eA * seQ[i*8+3] * cb[3];
        p1.x = eA * seQ[i*8+4] * cb[4];
        p1.y = eA * seQ[i*8+5] * cb[5];
        p1.z = eA * seQ[i*8+6] * cb[6];
        p1.w = eA * seQ[i*8+7] * cb[7];
        *(float4*)(out + pbase)     = p0;
        *(float4*)(out + pbase + 4) = p1;
    }
}

extern "C" void kernel_launch(void* const* d_in, const int* in_sizes, int n_in,
                              void* d_out, int out_size) {
    const float* z         = (const float*)d_in[0];
    const float* pi        = (const float*)d_in[1];
    const float* Q         = (const float*)d_in[2];
    const float* init_mean = (const float*)d_in[3];
    const float* init_cov  = (const float*)d_in[4];
    const float* covs      = (const float*)d_in[5];
    const float* W1        = (const float*)d_in[6];
    const float* b1        = (const float*)d_in[7];
    const float* W2        = (const float*)d_in[8];
    const float* b2        = (const float*)d_in[9];
    float* out = (float*)d_out;

    snlds_prep<<<1, 256>>>(pi, Q, init_cov, covs);
    snlds_emis<<<dim3((Bb*Tt)/128, Kk), 128>>>(z, W1, b1, W2, b2, init_mean);
    snlds_conv<<<(Bb*Tt)/256, 256>>>();
    snlds_p1<<<(Bb*CC*8)/256, 256>>>();
    snlds_p2<<<2, 64>>>();
    snlds_p3<<<dim3((Bb*CC)/256, 2), 256>>>();
    snlds_out<<<(Bb*Tt)/32, 256>>>(out);
}

// round 4
// speedup vs baseline: 2.8832x; 1.1236x over previous
#include <cuda_runtime.h>
#include <math.h>
#include <stdint.h>

#define Bb   64
#define Tt   2048
#define LDIM 16
#define HDIM 64
#define Kk   8
#define LC   32
#define CC   64              // Tt / LC

#define LOG2E  1.4426950408889634f
#define LN2F   0.6931471805599453f
#define LOG2PI 1.8378770664093453f

#define GSZ  (Bb*Tt*Kk)            // gamma elements
#define PSZ  (Bb*(Tt-1)*Kk*Kk)     // paired elements

typedef unsigned long long u64;

// ---------------- f32x2 helpers (sm_10x packed fp32) ----------------
__device__ __forceinline__ u64 fma2(u64 a, u64 b, u64 c){
    u64 d; asm("fma.rn.f32x2 %0, %1, %2, %3;" : "=l"(d) : "l"(a), "l"(b), "l"(c)); return d;
}
__device__ __forceinline__ u64 packbb(float x){
    u64 d; asm("mov.b64 %0, {%1, %1};" : "=l"(d) : "f"(x)); return d;
}
__device__ __forceinline__ u64 pack2(float x, float y){
    u64 d; asm("mov.b64 %0, {%1, %2};" : "=l"(d) : "f"(x), "f"(y)); return d;
}
__device__ __forceinline__ float2 unpk(u64 u){
    float2 f; asm("mov.b64 {%0, %1}, %2;" : "=f"(f.x), "=f"(f.y) : "l"(u)); return f;
}

// ---------------- scratch (__device__ globals: graph/alloc-rule safe) ----------------
__device__ __align__(16) float g_le [Bb*Tt*Kk];   // emissions log-prob
__device__ __align__(16) float g_ele[Bb*Tt*Kk];   // exp(le - m_t)  (linear, <=1)
__device__ float g_m  [Bb*Tt];                    // m_t = max_k le
__device__ __align__(16) float g_A  [Bb*Tt*Kk];   // a-hat (scaled forward)
__device__ __align__(16) float g_Bv [Bb*Tt*Kk];   // b-hat (scaled backward)
__device__ float g_sig[Bb*Tt];                    // sum_k a-hat_t
__device__ int   g_E  [Bb*Tt];                    // forward cumulative pow2 exponent
__device__ int   g_F  [Bb*Tt];                    // backward cumulative pow2 exponent
__device__ __align__(16) float g_M  [Bb*CC*64];   // chunk matrices
__device__ int   g_EM [Bb*CC];                    // chunk matrix exponents
__device__ __align__(16) float g_bndA[Bb*CC*8];   // forward boundary vectors
__device__ int   g_EA [Bb*CC];
__device__ __align__(16) float g_bndW[Bb*CC*8];   // backward boundary vectors
__device__ int   g_FW [Bb*CC];
__device__ float g_eQ [64];
__device__ float g_epi[8];
__device__ float g_Qlog[64];
__device__ float g_logpi[8];
__device__ float g_Linv0[Kk*LDIM*LDIM];
__device__ float g_LinvT[Kk*LDIM*LDIM];
__device__ float g_ld0[Kk];
__device__ float g_ldT[Kk];

// rescale 8-vector by 2^-e where e = exponent of max; returns e. (lossless)
__device__ __forceinline__ int rescale8(float* v) {
    float mx = v[0];
    #pragma unroll
    for (int k = 1; k < 8; k++) mx = fmaxf(mx, v[k]);
    int ib = __float_as_int(mx);
    int ee = (ib >> 23) - 127;
    float sc = __int_as_float((254 - (ib >> 23)) << 23);
    #pragma unroll
    for (int k = 0; k < 8; k++) v[k] *= sc;
    return ee;
}

__device__ __forceinline__ void load8(float* dst, const float* src) {
    float4 a = *(const float4*)src;
    float4 b = *(const float4*)(src + 4);
    dst[0]=a.x; dst[1]=a.y; dst[2]=a.z; dst[3]=a.w;
    dst[4]=b.x; dst[5]=b.y; dst[6]=b.z; dst[7]=b.w;
}
__device__ __forceinline__ void store8(float* dst, const float* v) {
    *(float4*)dst       = make_float4(v[0], v[1], v[2], v[3]);
    *(float4*)(dst + 4) = make_float4(v[4], v[5], v[6], v[7]);
}

// ---------------- prep: cholesky terms + log-softmax + linear tables ----------------
__global__ void snlds_prep(const float* __restrict__ pi,
                           const float* __restrict__ Q,
                           const float* __restrict__ init_cov,
                           const float* __restrict__ covs)
{
    __shared__ float S[16][256];   // 16 matrices (8 init + 8 trans), 16x16
    int tid = threadIdx.x;         // 256 threads

    for (int e = tid; e < 4096; e += 256) {
        int m  = e >> 8;
        int ij = e & 255;
        int i  = ij >> 4, j = ij & 15;
        const float* C = (m < 8) ? (init_cov + m*256) : (covs + (m-8)*256);
        float s = (i == j) ? 1e-6f : 0.0f;
        #pragma unroll
        for (int d = 0; d < 16; d++) s = fmaf(C[i*16+d], C[j*16+d], s);
        S[m][ij] = s;
    }
    __syncthreads();

    int m = tid >> 4, r = tid & 15;
    for (int kk = 0; kk < 16; kk++) {
        if (r == kk) {
            float s = S[m][kk*16+kk];
            for (int e2 = 0; e2 < kk; e2++) { float v = S[m][kk*16+e2]; s -= v*v; }
            S[m][kk*16+kk] = sqrtf(s);
        }
        __syncthreads();
        if (r > kk) {
            float s = S[m][r*16+kk];
            for (int e2 = 0; e2 < kk; e2++) s -= S[m][r*16+e2]*S[m][kk*16+e2];
            S[m][r*16+kk] = s / S[m][kk*16+kk];
        }
        __syncthreads();
    }

    if (r == 0) {
        float s = 0.f;
        for (int d = 0; d < 16; d++) s += logf(S[m][d*16+d]);
        if (m < 8) g_ld0[m] = s; else g_ldT[m-8] = s;
    }

    {
        int c = r;
        float x[16];
        #pragma unroll
        for (int i2 = 0; i2 < 16; i2++) x[i2] = 0.f;
        for (int i2 = c; i2 < 16; i2++) {
            float s = (i2 == c) ? 1.0f : 0.0f;
            for (int e2 = c; e2 < i2; e2++) s -= S[m][i2*16+e2]*x[e2];
            x[i2] = s / S[m][i2*16+i2];
        }
        float* dst = (m < 8) ? (g_Linv0 + m*256) : (g_LinvT + (m-8)*256);
        for (int i2 = 0; i2 < 16; i2++) dst[i2*16 + c] = x[i2];
    }

    if (tid < 8) {
        float mx = -1e30f;
        for (int j = 0; j < 8; j++) mx = fmaxf(mx, Q[tid*8+j]);
        float se = 0.f;
        for (int j = 0; j < 8; j++) se += expf(Q[tid*8+j]-mx);
        float l = mx + logf(se);
        for (int j = 0; j < 8; j++) g_Qlog[tid*8+j] = Q[tid*8+j] - l;
    }
    if (tid == 8) {
        float mx = -1e30f;
        for (int j = 0; j < 8; j++) mx = fmaxf(mx, pi[j]);
        float se = 0.f;
        for (int j = 0; j < 8; j++) se += expf(pi[j]-mx);
        float l = mx + logf(se);
        for (int j = 0; j < 8; j++) g_logpi[j] = pi[j] - l;
    }
    __syncthreads();
    if (tid < 64) g_eQ[tid] = exp2f(g_Qlog[tid] * LOG2E);
    if (tid < 8)  g_epi[tid] = exp2f(g_logpi[tid] * LOG2E);
}

// ---------------- emissions (f32x2-packed) ----------------
__global__ void __launch_bounds__(128) snlds_emis(const float* __restrict__ z,
                                                  const float* __restrict__ W1,
                                                  const float* __restrict__ b1,
                                                  const float* __restrict__ W2,
                                                  const float* __restrict__ b2,
                                                  const float* __restrict__ init_mean)
{
    int k  = blockIdx.y;
    int tx = threadIdx.x;
    // transposed layouts so f32x2 operand pairs are contiguous
    __shared__ __align__(16) float sW1T[LDIM*HDIM];   // [d][j]   = W1[k][j][d]
    __shared__ __align__(16) float sW2J[HDIM*LDIM];   // [j][d]   = ln2 * W2[k][d][j]
    __shared__ __align__(16) float sLvT[256];         // [e][d]   = LinvT[d][e]
    __shared__ __align__(16) float sLv0T[256];        // [e][d]   = Linv0[d][e]
    __shared__ __align__(16) float sb1[HDIM];
    __shared__ __align__(16) float sb2[LDIM];
    __shared__ __align__(16) float sMean[LDIM];
    __shared__ float sld[2];

    for (int i = tx; i < HDIM*LDIM; i += 128) {
        int j = i >> 4, d = i & 15;
        sW1T[d*64 + j] = W1[k*HDIM*LDIM + i];                    // i = j*16+d
        sW2J[i]        = LN2F * W2[k*LDIM*HDIM + d*HDIM + j];    // W2[k][d][j]
    }
    for (int i = tx; i < 256; i += 128) {
        int d = i >> 4, e = i & 15;
        sLvT [e*16 + d] = g_LinvT[k*256 + i];
        sLv0T[e*16 + d] = g_Linv0[k*256 + i];
    }
    if (tx < HDIM) sb1[tx] = b1[k*HDIM+tx];
    if (tx < LDIM) { sb2[tx] = b2[k*LDIM+tx]; sMean[tx] = init_mean[k*LDIM+tx]; }
    if (tx == 0) { sld[0] = g_ld0[k]; sld[1] = g_ldT[k]; }
    __syncthreads();

    int idx = blockIdx.x*128 + tx;      // over B*T
    int t   = idx & (Tt-1);

    const float* zc = z + (size_t)idx*LDIM;
    const float* zp = (t == 0) ? zc : (zc - LDIM);   // clamp avoids OOB at idx==0

    // load zp, build broadcast pairs
    u64 zpp[16];
    {
        float tmp[16];
        load8(tmp, zp); load8(tmp+8, zp+8);
        #pragma unroll
        for (int d = 0; d < 16; d++) zpp[d] = packbb(tmp[d]);
    }
    // load zc, build lane pairs
    u64 zc2[8];
    {
        float tmp[16];
        load8(tmp, zc); load8(tmp+8, zc+8);
        #pragma unroll
        for (int d2 = 0; d2 < 8; d2++) zc2[d2] = pack2(tmp[2*d2], tmp[2*d2+1]);
    }

    // mu accumulators: lanes = (d, d+1), init with b2 pairs
    u64 mu2[8];
    #pragma unroll
    for (int d2 = 0; d2 < 8; d2++) mu2[d2] = *(const u64*)(sb2 + 2*d2);

    // MLP: for each group of 4 hidden units, matvec (lanes=(j,j+1)), softplus, accumulate
    #pragma unroll 2
    for (int j = 0; j < HDIM; j += 4) {
        u64 aA = *(const u64*)(sb1 + j);
        u64 aB = *(const u64*)(sb1 + j + 2);
        #pragma unroll
        for (int d = 0; d < 16; d++) {
            aA = fma2(*(const u64*)(sW1T + d*64 + j),     zpp[d], aA);
            aB = fma2(*(const u64*)(sW1T + d*64 + j + 2), zpp[d], aB);
        }
        float2 fA = unpk(aA), fB = unpk(aB);
        // softplus in log2 domain; the ln2 factor is folded into sW2J
        float h0 = __log2f(1.0f + exp2f(fA.x * LOG2E));
        float h1 = __log2f(1.0f + exp2f(fA.y * LOG2E));
        float h2 = __log2f(1.0f + exp2f(fB.x * LOG2E));
        float h3 = __log2f(1.0f + exp2f(fB.y * LOG2E));
        u64 hb0 = packbb(h0), hb1 = packbb(h1), hb2 = packbb(h2), hb3 = packbb(h3);
        #pragma unroll
        for (int d2 = 0; d2 < 8; d2++) {
            mu2[d2] = fma2(*(const u64*)(sW2J + (j  )*16 + 2*d2), hb0, mu2[d2]);
            mu2[d2] = fma2(*(const u64*)(sW2J + (j+1)*16 + 2*d2), hb1, mu2[d2]);
            mu2[d2] = fma2(*(const u64*)(sW2J + (j+2)*16 + 2*d2), hb2, mu2[d2]);
            mu2[d2] = fma2(*(const u64*)(sW2J + (j+3)*16 + 2*d2), hb3, mu2[d2]);
        }
    }

    // diff = zc - mu  (or zc - mean at t==0)
    u64 neg1 = pack2(-1.0f, -1.0f);
    u64 diff2[8];
    #pragma unroll
    for (int d2 = 0; d2 < 8; d2++) diff2[d2] = fma2(mu2[d2], neg1, zc2[d2]);
    float ldh = sld[1];
    const float* LT = sLvT;
    if (t == 0) {
        #pragma unroll
        for (int d2 = 0; d2 < 8; d2++)
            diff2[d2] = fma2(*(const u64*)(sMean + 2*d2), neg1, zc2[d2]);
        ldh = sld[0]; LT = sLv0T;
    }

    // broadcast diff values
    u64 dbb[16];
    #pragma unroll
    for (int d2 = 0; d2 < 8; d2++) {
        float2 f = unpk(diff2[d2]);
        dbb[2*d2]   = packbb(f.x);
        dbb[2*d2+1] = packbb(f.y);
    }

    // y = Linv * diff, lanes = (d, d+1)
    u64 y2[8];
    #pragma unroll
    for (int d2 = 0; d2 < 8; d2++) y2[d2] = 0ull;
    #pragma unroll
    for (int e = 0; e < 16; e++) {
        #pragma unroll
        for (int d2 = 0; d2 < 8; d2++)
            y2[d2] = fma2(*(const u64*)(LT + e*16 + 2*d2), dbb[e], y2[d2]);
    }
    u64 m2 = 0ull;
    #pragma unroll
    for (int d2 = 0; d2 < 8; d2++) m2 = fma2(y2[d2], y2[d2], m2);
    float2 mm = unpk(m2);
    float maha = mm.x + mm.y;

    g_le[(size_t)idx*Kk + k] = -0.5f*maha - ldh - 0.5f*LDIM*LOG2PI;
}

// ---------------- conversion: m_t = max_k le, ele = exp(le - m) ----------------
__global__ void __launch_bounds__(256) snlds_conv()
{
    int bt = blockIdx.x*256 + threadIdx.x;
    float v[8];
    load8(v, g_le + (size_t)bt*8);
    float m = v[0];
    #pragma unroll
    for (int k = 1; k < 8; k++) m = fmaxf(m, v[k]);
    g_m[bt] = m;
    float mL = m * LOG2E;
    #pragma unroll
    for (int k = 0; k < 8; k++) v[k] = exp2f(fmaf(v[k], LOG2E, -mL));
    store8(g_ele + (size_t)bt*8, v);
}

// ---------------- phase 1: per-chunk 8x8 matrix products (one row per thread) ----------------
__global__ void __launch_bounds__(256) snlds_p1()
{
    int gt = blockIdx.x*256 + threadIdx.x;   // Bb*CC*8 threads
    int i = gt & 7;
    int chain = gt >> 3;                     // b*CC + c
    int c = chain & (CC-1);
    int b = chain >> 6;

    float q[64];
    #pragma unroll
    for (int e = 0; e < 64; e++) q[e] = g_eQ[e];

    float r[8];
    #pragma unroll
    for (int k = 0; k < 8; k++) r[k] = (k == i) ? 1.0f : 0.0f;
    int E = 0;

    const float* eb = g_ele + ((size_t)b*Tt)*8;
    int t0 = c*LC + ((c == 0) ? 1 : 0);
    int t1 = c*LC + LC;

    float el[8];
    load8(el, eb + (size_t)t0*8);
    for (int t = t0; t < t1; t++) {
        float eln[8];
        int tn = (t+1 < t1) ? (t+1) : t;
        load8(eln, eb + (size_t)tn*8);       // prefetch next step
        float n[8];
        #pragma unroll
        for (int k = 0; k < 8; k++) {
            float s = r[0]*q[0*8+k];
            #pragma unroll
            for (int j = 1; j < 8; j++) s = fmaf(r[j], q[j*8+k], s);
            n[k] = s * el[k];
        }
        E += rescale8(n);
        #pragma unroll
        for (int k = 0; k < 8; k++) { r[k] = n[k]; el[k] = eln[k]; }
    }

    const unsigned FULL = 0xffffffffu;
    int Emax = E;
    Emax = max(Emax, __shfl_xor_sync(FULL, Emax, 1));
    Emax = max(Emax, __shfl_xor_sync(FULL, Emax, 2));
    Emax = max(Emax, __shfl_xor_sync(FULL, Emax, 4));
    int d = E - Emax; if (d < -126) d = -126;
    float sc = __int_as_float((127 + d) << 23);
    #pragma unroll
    for (int k = 0; k < 8; k++) r[k] *= sc;
    store8(g_M + (size_t)chain*64 + i*8, r);
    if (i == 0) g_EM[chain] = Emax;
}

// ---------------- phase 2: serial chunk-boundary vectors ----------------
__global__ void snlds_p2()
{
    int b = threadIdx.x;                     // 64 threads per block
    if (blockIdx.x == 0) {
        float a[8]; int E = 0;
        const float* eb = g_ele + (size_t)b*Tt*8;
        #pragma unroll
        for (int k = 0; k < 8; k++) a[k] = g_epi[k] * eb[k];
        E = rescale8(a);
        store8(g_bndA + (size_t)(b*CC)*8, a);
        g_EA[b*CC] = E;

        float Mm[64];
        #pragma unroll
        for (int x = 0; x < 8; x++) load8(Mm + x*8, g_M + (size_t)(b*CC)*64 + x*8);
        for (int c = 0; c < CC-1; c++) {
            float Mn[64];
            int cn = (c+1 < CC-1) ? (c+1) : c;
            #pragma unroll
            for (int x = 0; x < 8; x++) load8(Mn + x*8, g_M + (size_t)(b*CC + cn)*64 + x*8);
            float n[8];
            #pragma unroll
            for (int k = 0; k < 8; k++) {
                float s = a[0]*Mm[0*8+k];
                #pragma unroll
                for (int i = 1; i < 8; i++) s = fmaf(a[i], Mm[i*8+k], s);
                n[k] = s;
            }
            E += rescale8(n) + g_EM[b*CC + c];
            #pragma unroll
            for (int k = 0; k < 8; k++) a[k] = n[k];
            store8(g_bndA + (size_t)(b*CC + c + 1)*8, a);
            g_EA[b*CC + c + 1] = E;
            #pragma unroll
            for (int x = 0; x < 64; x++) Mm[x] = Mn[x];
        }
    } else {
        float w[8]; int F = 0;
        #pragma unroll
        for (int k = 0; k < 8; k++) w[k] = 1.0f;
        store8(g_bndW + (size_t)(b*CC + CC-1)*8, w);
        g_FW[b*CC + CC-1] = 0;

        float Mm[64];
        #pragma unroll
        for (int x = 0; x < 8; x++) load8(Mm + x*8, g_M + (size_t)(b*CC + CC-1)*64 + x*8);
        for (int c = CC-1; c >= 1; c--) {
            float Mn[64];
            int cn = (c-1 > 1) ? (c-1) : 1;
            #pragma unroll
            for (int x = 0; x < 8; x++) load8(Mn + x*8, g_M + (size_t)(b*CC + cn)*64 + x*8);
            float n[8];
            #pragma unroll
            for (int i = 0; i < 8; i++) {
                float s = Mm[i*8+0]*w[0];
                #pragma unroll
                for (int k = 1; k < 8; k++) s = fmaf(Mm[i*8+k], w[k], s);
                n[i] = s;
            }
            F += rescale8(n) + g_EM[b*CC + c];
            #pragma unroll
            for (int k = 0; k < 8; k++) w[k] = n[k];
            store8(g_bndW + (size_t)(b*CC + c - 1)*8, w);
            g_FW[b*CC + c - 1] = F;
            #pragma unroll
            for (int x = 0; x < 64; x++) Mm[x] = Mn[x];
        }
    }
}

// ---------------- phase 3: within-chunk vector recursions (thread per chain) ----------------
__global__ void __launch_bounds__(256) snlds_p3()
{
    int chain = blockIdx.x*256 + threadIdx.x;  // Bb*CC chains
    int c = chain & (CC-1);
    int b = chain >> 6;

    float q[64];
    #pragma unroll
    for (int e = 0; e < 64; e++) q[e] = g_eQ[e];

    const float* eb = g_ele + (size_t)b*Tt*8;

    if (blockIdx.y == 0) {
        float a[8];
        load8(a, g_bndA + (size_t)chain*8);
        int E = g_EA[chain];
        float* Ad = g_A + (size_t)b*Tt*8;
        int t0 = c*LC;
        if (c == 0) {
            store8(Ad, a);
            float sg = a[0]+a[1]+a[2]+a[3]+a[4]+a[5]+a[6]+a[7];
            g_sig[b*Tt] = sg; g_E[b*Tt] = E;
            t0 = 1;
        }
        int t1 = c*LC + LC;
        float el[8];
        load8(el, eb + (size_t)t0*8);
        for (int t = t0; t < t1; t++) {
            float eln[8];
            int tn = (t+1 < t1) ? (t+1) : t;
            load8(eln, eb + (size_t)tn*8);
            float n[8];
            #pragma unroll
            for (int k = 0; k < 8; k++) {
                float s = a[0]*q[0*8+k];
                #pragma unroll
                for (int j = 1; j < 8; j++) s = fmaf(a[j], q[j*8+k], s);
                n[k] = s * el[k];
            }
            E += rescale8(n);
            #pragma unroll
            for (int k = 0; k < 8; k++) { a[k] = n[k]; el[k] = eln[k]; }
            store8(Ad + (size_t)t*8, a);
            float sg = a[0]+a[1]+a[2]+a[3]+a[4]+a[5]+a[6]+a[7];
            g_sig[b*Tt + t] = sg; g_E[b*Tt + t] = E;
        }
    } else {
        float w[8];
        load8(w, g_bndW + (size_t)chain*8);
        int F = g_FW[chain];
        float* Bd = g_Bv + (size_t)b*Tt*8;
        int thi = c*LC + LC - 1;
        int lo  = c*LC;
        store8(Bd + (size_t)thi*8, w);
        g_F[b*Tt + thi] = F;
        float el[8];
        load8(el, eb + (size_t)thi*8);               // used at step t = thi-1 (needs el[t+1])
        for (int t = thi - 1; t >= lo; t--) {
            float eln[8];
            int tn = (t > lo) ? t : lo;
            load8(eln, eb + (size_t)tn*8);           // el[t] for next step
            float s8[8];
            #pragma unroll
            for (int j = 0; j < 8; j++) s8[j] = el[j] * w[j];
            float n[8];
            #pragma unroll
            for (int i = 0; i < 8; i++) {
                float s = q[i*8+0]*s8[0];
                #pragma unroll
                for (int j = 1; j < 8; j++) s = fmaf(q[i*8+j], s8[j], s);
                n[i] = s;
            }
            F += rescale8(n);
            #pragma unroll
            for (int k = 0; k < 8; k++) { w[k] = n[k]; el[k] = eln[k]; }
            store8(Bd + (size_t)t*8, w);
            g_F[b*Tt + t] = F;
        }
    }
}

// ---------------- outputs: gamma, paired, log_Z ----------------
__global__ void __launch_bounds__(256) snlds_out(float* __restrict__ out)
{
    const unsigned FULL = 0xffffffffu;
    __shared__ float seQ[64];
    int tid = threadIdx.x;
    if (tid < 64) seQ[tid] = g_eQ[tid];
    __syncthreads();

    int gidx = blockIdx.x*32 + (tid >> 3);  // (b,t) flat index
    int i    = tid & 7;
    int t    = gidx & (Tt-1);
    int b    = gidx >> 11;

    float ai = g_A [(size_t)gidx*8 + i];
    float bi = g_Bv[(size_t)gidx*8 + i];
    float pr = ai * bi;
    float G = pr;
    G += __shfl_xor_sync(FULL, G, 1);
    G += __shfl_xor_sync(FULL, G, 2);
    G += __shfl_xor_sync(FULL, G, 4);
    float rG = 1.0f / G;
    out[(size_t)gidx*8 + i] = pr * rG;                  // gamma

    if (i == 0) {                                       // log_Z
        float lz;
        if (t == 0) lz = (log2f(g_sig[gidx]) + (float)g_E[gidx]) * LN2F + g_m[gidx];
        else        lz = (log2f(g_sig[gidx]) - log2f(g_sig[gidx-1])
                          + (float)(g_E[gidx] - g_E[gidx-1])) * LN2F + g_m[gidx];
        out[(size_t)GSZ + PSZ + gidx] = lz;
    }

    // paired
    int gn = (t < Tt-1) ? (gidx + 1) : gidx;
    float bj = g_Bv [(size_t)gn*8 + i];
    float ej = g_ele[(size_t)gn*8 + i];
    float cj = bj * ej;
    int dF = g_F[gidx] - g_F[gn];
    int sb = 127 - dF; if (sb < 1) sb = 1; if (sb > 254) sb = 254;
    float pnorm = rG * __int_as_float(sb << 23);

    int baseLane = tid & 24;
    float cb[8];
    #pragma unroll
    for (int j = 0; j < 8; j++) cb[j] = __shfl_sync(FULL, cj, baseLane + j);

    if (t < Tt-1) {
        float eA = ai * pnorm;
        size_t pbase = (size_t)GSZ + ((size_t)(b*(Tt-1) + t))*64 + (size_t)i*8;
        float4 p0, p1;
        p0.x = eA * seQ[i*8+0] * cb[0];
        p0.y = eA * seQ[i*8+1] * cb[1];
        p0.z = eA * seQ[i*8+2] * cb[2];
        p0.w = eA * seQ[i*8+3] * cb[3];
        p1.x = eA * seQ[i*8+4] * cb[4];
        p1.y = eA * seQ[i*8+5] * cb[5];
        p1.z = eA * seQ[i*8+6] * cb[6];
        p1.w = eA * seQ[i*8+7] * cb[7];
        *(float4*)(out + pbase)     = p0;
        *(float4*)(out + pbase + 4) = p1;
    }
}

extern "C" void kernel_launch(void* const* d_in, const int* in_sizes, int n_in,
                              void* d_out, int out_size) {
    const float* z         = (const float*)d_in[0];
    const float* pi        = (const float*)d_in[1];
    const float* Q         = (const float*)d_in[2];
    const float* init_mean = (const float*)d_in[3];
    const float* init_cov  = (const float*)d_in[4];
    const float* covs      = (const float*)d_in[5];
    const float* W1        = (const float*)d_in[6];
    const float* b1        = (const float*)d_in[7];
    const float* W2        = (const float*)d_in[8];
    const float* b2        = (const float*)d_in[9];
    float* out = (float*)d_out;

    snlds_prep<<<1, 256>>>(pi, Q, init_cov, covs);
    snlds_emis<<<dim3((Bb*Tt)/128, Kk), 128>>>(z, W1, b1, W2, b2, init_mean);
    snlds_conv<<<(Bb*Tt)/256, 256>>>();
    snlds_p1<<<(Bb*CC*8)/256, 256>>>();
    snlds_p2<<<2, 64>>>();
    snlds_p3<<<dim3((Bb*CC)/256, 2), 256>>>();
    snlds_out<<<(Bb*Tt)/32, 256>>>(out);
}